// round 10
// baseline (speedup 1.0000x reference)
#include <cuda_runtime.h>
#include <cstdint>

typedef unsigned long long ull;
#define FULLMASK 0xffffffffu

constexpr int MAX_ITER = 8192;
constexpr int NNODES   = MAX_ITER + 1;   // 8193
constexpr int NBLK     = 256;            // 32 iterations per block
constexpr int NTHREADS = 1024;           // 32 warps
constexpr int CSIZE    = 8;
constexpr int SERIAL_WARP = 31;

constexpr int NODES_PAD = 8208;          // 8193 + sentinel pad (scan reads < 8208)
constexpr int NSLOT_PAD = 34;            // 0..30 samples, 31/32 = sample-31 halves

// per-CTA smem layout:
//   nodes float2[8208] | samps float2[8192] | bests ull[4][8][34]
//   P ull[4][32] (delta partials, ring-4) | cand float2[2][32]
//   mbars ull[12]: [0..3]=nodes ring, [4..7]=bests objs, [8..11]=P ring
constexpr size_t OFF_SAMPS = (size_t)NODES_PAD * sizeof(float2);
constexpr size_t OFF_BESTS = OFF_SAMPS + (size_t)MAX_ITER * sizeof(float2);
constexpr size_t OFF_P     = OFF_BESTS + 4ull * CSIZE * NSLOT_PAD * sizeof(ull);
constexpr size_t OFF_CAND  = OFF_P + 4ull * 32 * sizeof(ull);
constexpr size_t OFF_MBARS = OFF_CAND + 64ull * sizeof(float2);
constexpr size_t SMEM_BYTES = OFF_MBARS + 12ull * sizeof(ull);

constexpr ull KEY_INF = ((ull)0x7f800000u << 32);

__device__ __forceinline__ uint32_t smem_u32(const void* p) {
    return (uint32_t)__cvta_generic_to_shared(p);
}
__device__ __forceinline__ uint32_t my_ctarank() {
    uint32_t r; asm("mov.u32 %0, %%cluster_ctarank;" : "=r"(r)); return r;
}
__device__ __forceinline__ uint32_t mapa_u32(uint32_t laddr, uint32_t rank) {
    uint32_t r; asm("mapa.shared::cluster.u32 %0, %1, %2;" : "=r"(r) : "r"(laddr), "r"(rank));
    return r;
}
__device__ __forceinline__ void st_cluster_u64(uint32_t raddr, ull v) {
    asm volatile("st.shared::cluster.u64 [%0], %1;" :: "r"(raddr), "l"(v) : "memory");
}
__device__ __forceinline__ void mbar_init(uint32_t a, uint32_t cnt) {
    asm volatile("mbarrier.init.shared.b64 [%0], %1;" :: "r"(a), "r"(cnt) : "memory");
}
__device__ __forceinline__ void mbar_arrive_cta(uint32_t a) {
    asm volatile("mbarrier.arrive.release.cta.shared::cta.b64 _, [%0];" :: "r"(a) : "memory");
}
__device__ __forceinline__ void mbar_arrive_cluster_remote(uint32_t raddr) {
    asm volatile("mbarrier.arrive.release.cluster.shared::cluster.b64 _, [%0];"
                 :: "r"(raddr) : "memory");
}
__device__ __forceinline__ void mbar_wait_cta(uint32_t a, uint32_t phase) {
    asm volatile(
        "{\n\t.reg .pred P;\n\t"
        "WL_%=:\n\t"
        "mbarrier.try_wait.parity.acquire.cta.shared::cta.b64 P, [%0], %1, 0x989680;\n\t"
        "@P bra.uni WD_%=;\n\t"
        "bra.uni WL_%=;\n\t"
        "WD_%=:\n\t}"
        :: "r"(a), "r"(phase) : "memory");
}
__device__ __forceinline__ void mbar_wait_cluster(uint32_t a, uint32_t phase) {
    asm volatile(
        "{\n\t.reg .pred P;\n\t"
        "WL_%=:\n\t"
        "mbarrier.try_wait.parity.acquire.cluster.shared::cta.b64 P, [%0], %1, 0x989680;\n\t"
        "@P bra.uni WD_%=;\n\t"
        "bra.uni WL_%=;\n\t"
        "WD_%=:\n\t}"
        :: "r"(a), "r"(phase) : "memory");
}
#define CLUSTER_ARRIVE() asm volatile("barrier.cluster.arrive.aligned;" ::: "memory")
#define CLUSTER_WAIT()   asm volatile("barrier.cluster.wait.aligned;"   ::: "memory")

__device__ __forceinline__ ull bfly_min(ull key) {
    #pragma unroll
    for (int o = 16; o > 0; o >>= 1) {
        ull other = __shfl_xor_sync(FULLMASK, key, o);
        key = (other < key) ? other : key;
    }
    return key;
}

__device__ __forceinline__ void steer(float fx, float fy, float sx, float sy, float d2,
                                      float& ox, float& oy) {
    float dist = __fsqrt_rn(__fadd_rn(d2, 1e-12f));
    float q    = __fdiv_rn(5.0f, dist);
    float sc   = (dist > 5.0f) ? q : 1.0f;
    ox = __fadd_rn(fx, __fmul_rn(__fadd_rn(sx, -fx), sc));
    oy = __fadd_rn(fy, __fmul_rn(__fadd_rn(sy, -fy), sc));
}

__device__ __forceinline__ float d2_rn(float nx, float ny, float sx, float sy) {
    float dx = __fadd_rn(nx, -sx), dy = __fadd_rn(ny, -sy);
    return __fadd_rn(__fmul_rn(dx, dx), __fmul_rn(dy, dy));
}

// per-lane scan partial, 128-node tiles; sentinels/races benign (u64 keys exact)
__device__ __forceinline__ ull scan_part(const float2* __restrict__ nodes_s, float2 s,
                                         int bound, int t0, int tstep, int lane) {
    const float INF = __int_as_float(0x7f800000);
    float bd2 = INF; int bidx = 0;
    for (int t = t0; 128 * t <= bound; t += tstep) {
        int i0 = 128 * t + 2 * lane;
        float4 a = *reinterpret_cast<const float4*>(&nodes_s[i0]);
        float4 c = *reinterpret_cast<const float4*>(&nodes_s[i0 + 64]);
        float da0 = d2_rn(a.x, a.y, s.x, s.y);
        float da1 = d2_rn(a.z, a.w, s.x, s.y);
        float dc0 = d2_rn(c.x, c.y, s.x, s.y);
        float dc1 = d2_rn(c.z, c.w, s.x, s.y);
        float ma = fminf(da0, da1); int ia = (da0 <= da1) ? i0 : i0 + 1;
        float mc = fminf(dc0, dc1); int ic = (dc0 <= dc1) ? i0 + 64 : i0 + 65;
        float m  = fminf(ma, mc);   int mi = (ma <= mc) ? ia : ic;
        if (m < bd2) { bd2 = m; bidx = mi; }
    }
    return ((ull)__float_as_uint(bd2) << 32) | (uint32_t)bidx;
}

__global__ void __launch_bounds__(NTHREADS, 1) __cluster_dims__(CSIZE, 1, 1)
rrt_kernel(const float* __restrict__ state,
           const float* __restrict__ goal,
           const float* __restrict__ u,
           const float* __restrict__ r,
           float* __restrict__ out)
{
    extern __shared__ char smem_raw[];
    float2* nodes_s = (float2*)smem_raw;
    float2* samps   = (float2*)(smem_raw + OFF_SAMPS);
    ull (*bests)[CSIZE][NSLOT_PAD] = (ull (*)[CSIZE][NSLOT_PAD])(smem_raw + OFF_BESTS);
    ull (*P)[32]    = (ull (*)[32])(smem_raw + OFF_P);     // ring-4
    float2* cand    = (float2*)(smem_raw + OFF_CAND);      // [2][32] ring
    ull* mbars      = (ull*)(smem_raw + OFF_MBARS);

    const int tid  = threadIdx.x;
    const int lane = tid & 31;
    const int warp = tid >> 5;
    const uint32_t crank = my_ctarank();
    const float INF = __int_as_float(0x7f800000);

    const uint32_t mb_nodes0 = smem_u32(&mbars[0]);   // 4 ring objs at +8*idx
    const uint32_t mb_bests0 = smem_u32(&mbars[4]);   // 4 objs
    const uint32_t mb_P0     = smem_u32(&mbars[8]);   // 4 ring objs

    // ---- init ----
    for (int i = tid; i < NODES_PAD; i += NTHREADS)
        nodes_s[i] = make_float2(INF, INF);
    const float gx = goal[0], gy = goal[1];
    for (int i = tid; i < MAX_ITER; i += NTHREADS) {
        float ui = u[i];
        float sx = __fmul_rn(r[2 * i],     200.0f);
        float sy = __fmul_rn(r[2 * i + 1], 200.0f);
        if (ui < 0.1f) { sx = gx; sy = gy; }
        samps[i] = make_float2(sx, sy);
    }
    if (tid < 64) cand[tid] = make_float2(INF, INF);
    if (tid == 0) {
        float2 st0 = make_float2(state[0], state[1]);
        nodes_s[0] = st0;
        // block "-1" ring half = parity 1; slot 31 <-> idx 32*0-31+31 = 0 = root
        cand[32 + 31] = st0;
        for (int o = 0; o < 4; o++) {
            mbar_init(mb_nodes0 + 8 * o, 32);          // serial warp lanes
            mbar_init(mb_bests0 + 8 * o, 33 * CSIZE);  // 33 slots x 8 src CTAs
            mbar_init(mb_P0 + 8 * o, 31);              // scan warps' lane-0
        }
    }
    __syncthreads();
    CLUSTER_ARRIVE();
    CLUSTER_WAIT();

    for (int b = 0; b < NBLK; b++) {
        if (warp == SERIAL_WARP) {
            // ===== serial warp: block b =====
            const float2 s2 = samps[32 * b + lane];
            const float sx = s2.x, sy = s2.y;

            // hoisted waits (both plenty of slack) + early loads
            ull pk = KEY_INF;
            if (b >= 1) {
                mbar_wait_cta(mb_P0 + 8 * ((b - 1) & 3), ((b - 1) >> 2) & 1);
                pk = P[(b - 1) & 3][lane];             // covers (32b-64, 32b-32]
            }
            ull bk = KEY_INF;
            if (b >= 2) {
                const int obj = (b - 2) & 3;
                mbar_wait_cluster(mb_bests0 + 8 * obj, ((b - 2) >> 2) & 1);
                #pragma unroll
                for (int c = 0; c < CSIZE; c++) {      // covers [0, 32b-64]
                    ull k2 = bests[obj][c][lane];
                    bk = (k2 < bk) ? k2 : bk;
                }
                if (lane == 31) {
                    #pragma unroll
                    for (int c = 0; c < CSIZE; c++) {
                        ull k2 = bests[obj][c][32];
                        bk = (k2 < bk) ? k2 : bk;
                    }
                }
            }

            // delta32 over block b-1's candidates (own cand ring half (b-1)&1)
            float bd2 = INF; int bidx = 0;
            {
                const float4* newh = (const float4*)(cand + 32 * ((b - 1) & 1));
                #pragma unroll
                for (int l = 0; l < 32; l += 2) {
                    float4 c = newh[l >> 1];
                    float d0 = d2_rn(c.x, c.y, sx, sy);
                    float d1 = d2_rn(c.z, c.w, sx, sy);
                    if (d0 < bd2) { bd2 = d0; bidx = 32 * b - 31 + l; }
                    if (d1 < bd2) { bd2 = d1; bidx = 32 * b - 31 + l + 1; }
                }
            }
            // exact u64 merge: delta, P, bests cover disjoint decreasing-idx ranges
            ull kk = ((ull)__float_as_uint(bd2) << 32) | (uint32_t)bidx;
            kk = (pk < kk) ? pk : kk;
            kk = (bk < kk) ? bk : kk;
            bd2  = __uint_as_float((uint32_t)(kk >> 32));
            bidx = (int)(uint32_t)kk;

            float2 f = nodes_s[bidx];
            float cx, cy;
            steer(f.x, f.y, sx, sy, bd2, cx, cy);

            // speculative fixup; working buffer = ring half b&1
            float2* wcand = cand + 32 * (b & 1);
            const float4* wcand4 = (const float4*)wcand;
            while (true) {
                wcand[lane] = make_float2(cx, cy);
                __syncwarp();
                float vmin = INF; int vl = 0;
                #pragma unroll
                for (int l = 0; l < 32; l += 2) {
                    float4 c = wcand4[l >> 1];
                    float e0 = d2_rn(c.x, c.y, sx, sy);
                    float e1 = d2_rn(c.z, c.w, sx, sy);
                    if (l     < lane && e0 < vmin) { vmin = e0; vl = l; }
                    if (l + 1 < lane && e1 < vmin) { vmin = e1; vl = l + 1; }
                }
                unsigned mask = __ballot_sync(FULLMASK, vmin < bd2);   // strict <
                if (!mask) break;
                int F2 = __ffs((int)mask) - 1;
                if (lane == F2) {
                    bd2 = vmin;
                    float2 c = wcand[vl];
                    steer(c.x, c.y, sx, sy, bd2, cx, cy);
                }
            }
            __syncwarp();
            nodes_s[32 * b + 1 + lane] = make_float2(cx, cy);
            if (b < NBLK - 1)
                mbar_arrive_cta(mb_nodes0 + 8 * (b & 3));   // all 32 lanes
        } else {
            // ===== scan warps (0..30): iteration j = b =====
            const int j = b;
            if (j >= 1 && j <= NBLK - 2)               // nodes [0,32j] final
                mbar_wait_cta(mb_nodes0 + 8 * ((j - 1) & 3), ((j - 1) >> 2) & 1);

            // ---- P(j+1): min over block j-1's 32 nodes, right after wake ----
            if (j <= NBLK - 2) {
                int nidx = 32 * j - 31 + lane;         // j=0 -> only lane31 = root
                float2 n = nodes_s[nidx >= 0 ? nidx : 0];
                {
                    const float2 s = samps[32 * (j + 1) + warp];
                    ull key = KEY_INF;
                    if (nidx >= 0) {
                        float d2 = d2_rn(n.x, n.y, s.x, s.y);
                        key = ((ull)__float_as_uint(d2) << 32) | (uint32_t)nidx;
                    }
                    key = bfly_min(key);
                    if (lane == 0) P[j & 3][warp] = key;
                }
                if (warp == 30) {                      // P slot 31
                    const float2 s = samps[32 * (j + 1) + 31];
                    ull key = KEY_INF;
                    if (nidx >= 0) {
                        float d2 = d2_rn(n.x, n.y, s.x, s.y);
                        key = ((ull)__float_as_uint(d2) << 32) | (uint32_t)nidx;
                    }
                    key = bfly_min(key);
                    if (lane == 0) P[j & 3][31] = key;
                }
                if (lane == 0) mbar_arrive_cta(mb_P0 + 8 * (j & 3));
            }

            // ---- scan + cross-CTA send for bests(j+2) (slack-filled) ----
            if (j <= NBLK - 3) {
                const int obj = j & 3;
                ull pk2 = scan_part(nodes_s, samps[32 * (j + 2) + warp],
                                    32 * j, (int)crank, CSIZE, lane);
                pk2 = bfly_min(pk2);
                if (lane < CSIZE) {
                    uint32_t la = smem_u32(&bests[obj][crank][warp]);
                    st_cluster_u64(mapa_u32(la, (uint32_t)lane), pk2);
                    mbar_arrive_cluster_remote(mapa_u32(mb_bests0 + 8 * obj, (uint32_t)lane));
                }
                if (warp == 29 || warp == 30) {        // sample-31 scan halves
                    int t0 = (warp == 29) ? (int)crank : (int)crank + CSIZE;
                    ull pk3 = scan_part(nodes_s, samps[32 * (j + 2) + 31],
                                        32 * j, t0, 2 * CSIZE, lane);
                    pk3 = bfly_min(pk3);
                    int slot = (warp == 29) ? 31 : 32;
                    if (lane < CSIZE) {
                        uint32_t la = smem_u32(&bests[obj][crank][slot]);
                        st_cluster_u64(mapa_u32(la, (uint32_t)lane), pk3);
                        mbar_arrive_cluster_remote(mapa_u32(mb_bests0 + 8 * obj, (uint32_t)lane));
                    }
                }
            }
        }
    }

    __syncthreads();
    CLUSTER_ARRIVE();
    CLUSTER_WAIT();

    if (crank == 0) {
        const float* ns = reinterpret_cast<const float*>(nodes_s);
        for (int i = tid; i < 2 * NNODES; i += NTHREADS)
            out[i] = ns[i];
    }
}

extern "C" void kernel_launch(void* const* d_in, const int* in_sizes, int n_in,
                              void* d_out, int out_size)
{
    const float* state = (const float*)d_in[0];
    const float* goal  = (const float*)d_in[1];
    const float* u     = (const float*)d_in[2];
    const float* r     = (const float*)d_in[3];
    float* out = (float*)d_out;

    cudaFuncSetAttribute(rrt_kernel,
                         cudaFuncAttributeMaxDynamicSharedMemorySize,
                         (int)SMEM_BYTES);
    rrt_kernel<<<CSIZE, NTHREADS, SMEM_BYTES>>>(state, goal, u, r, out);
}

// round 12
// speedup vs baseline: 1.3036x; 1.3036x over previous
#include <cuda_runtime.h>
#include <cstdint>

typedef unsigned long long ull;
#define FULLMASK 0xffffffffu

constexpr int MAX_ITER = 8192;
constexpr int NNODES   = MAX_ITER + 1;   // 8193
constexpr int NBLK     = 256;            // 32 iterations per block
constexpr int NTHREADS = 1024;           // 32 warps
constexpr int CSIZE    = 8;
constexpr int SERIAL_WARP = 31;

constexpr int NODES_PAD = 8208;          // 8193 + sentinel pad (scan reads < 8208)
constexpr int NSLOT_PAD = 34;            // 0..30 samples, 31/32 = sample-31 halves

// per-CTA smem layout:
//   nodes float2[8208] | samps float2[8192] | bests ull[4][8][34]
//   cand float2[2][32] (ring of block candidates)
//   mbars ull[8]: [0..3]=nodes ring objs, [4..7]=bests objs
constexpr size_t OFF_SAMPS = (size_t)NODES_PAD * sizeof(float2);
constexpr size_t OFF_BESTS = OFF_SAMPS + (size_t)MAX_ITER * sizeof(float2);
constexpr size_t OFF_CAND  = OFF_BESTS + 4ull * CSIZE * NSLOT_PAD * sizeof(ull);
constexpr size_t OFF_MBARS = OFF_CAND + 64ull * sizeof(float2);
constexpr size_t SMEM_BYTES = OFF_MBARS + 8ull * sizeof(ull);

constexpr ull KEY_INF = ((ull)0x7f800000u << 32);

__device__ __forceinline__ uint32_t smem_u32(const void* p) {
    return (uint32_t)__cvta_generic_to_shared(p);
}
__device__ __forceinline__ uint32_t my_ctarank() {
    uint32_t r; asm("mov.u32 %0, %%cluster_ctarank;" : "=r"(r)); return r;
}
__device__ __forceinline__ uint32_t mapa_u32(uint32_t laddr, uint32_t rank) {
    uint32_t r; asm("mapa.shared::cluster.u32 %0, %1, %2;" : "=r"(r) : "r"(laddr), "r"(rank));
    return r;
}
__device__ __forceinline__ void st_cluster_u64(uint32_t raddr, ull v) {
    asm volatile("st.shared::cluster.u64 [%0], %1;" :: "r"(raddr), "l"(v) : "memory");
}
__device__ __forceinline__ void mbar_init(uint32_t a, uint32_t cnt) {
    asm volatile("mbarrier.init.shared.b64 [%0], %1;" :: "r"(a), "r"(cnt) : "memory");
}
__device__ __forceinline__ void mbar_arrive_cta(uint32_t a) {
    asm volatile("mbarrier.arrive.release.cta.shared::cta.b64 _, [%0];" :: "r"(a) : "memory");
}
__device__ __forceinline__ void mbar_arrive_cluster_remote(uint32_t raddr) {
    asm volatile("mbarrier.arrive.release.cluster.shared::cluster.b64 _, [%0];"
                 :: "r"(raddr) : "memory");
}
__device__ __forceinline__ void mbar_wait_cta(uint32_t a, uint32_t phase) {
    asm volatile(
        "{\n\t.reg .pred P;\n\t"
        "WL_%=:\n\t"
        "mbarrier.try_wait.parity.acquire.cta.shared::cta.b64 P, [%0], %1, 0x989680;\n\t"
        "@P bra.uni WD_%=;\n\t"
        "bra.uni WL_%=;\n\t"
        "WD_%=:\n\t}"
        :: "r"(a), "r"(phase) : "memory");
}
__device__ __forceinline__ void mbar_wait_cluster(uint32_t a, uint32_t phase) {
    asm volatile(
        "{\n\t.reg .pred P;\n\t"
        "WL_%=:\n\t"
        "mbarrier.try_wait.parity.acquire.cluster.shared::cta.b64 P, [%0], %1, 0x989680;\n\t"
        "@P bra.uni WD_%=;\n\t"
        "bra.uni WL_%=;\n\t"
        "WD_%=:\n\t}"
        :: "r"(a), "r"(phase) : "memory");
}
#define CLUSTER_ARRIVE() asm volatile("barrier.cluster.arrive.aligned;" ::: "memory")
#define CLUSTER_WAIT()   asm volatile("barrier.cluster.wait.aligned;"   ::: "memory")

__device__ __forceinline__ ull bfly_min(ull key) {
    #pragma unroll
    for (int o = 16; o > 0; o >>= 1) {
        ull other = __shfl_xor_sync(FULLMASK, key, o);
        key = (other < key) ? other : key;
    }
    return key;
}

__device__ __forceinline__ ull umin64(ull a, ull b) { return (b < a) ? b : a; }

// (d,i) pair combine: left operand MUST cover the smaller index range;
// <= keeps the earliest index on ties (exact reference argmin order).
__device__ __forceinline__ void dimin(float& d, int& i, float d2, int i2) {
    bool p = (d <= d2);
    d = p ? d : d2;
    i = p ? i : i2;
}

// depth-4 min-tree over 16 (d,i) pairs, k-order = increasing index ranges
__device__ __forceinline__ void tree16(float* dp, int* ip, float& do_, int& io_) {
    dimin(dp[0], ip[0], dp[1], ip[1]);    dimin(dp[2], ip[2], dp[3], ip[3]);
    dimin(dp[4], ip[4], dp[5], ip[5]);    dimin(dp[6], ip[6], dp[7], ip[7]);
    dimin(dp[8], ip[8], dp[9], ip[9]);    dimin(dp[10], ip[10], dp[11], ip[11]);
    dimin(dp[12], ip[12], dp[13], ip[13]);dimin(dp[14], ip[14], dp[15], ip[15]);
    dimin(dp[0], ip[0], dp[2], ip[2]);    dimin(dp[4], ip[4], dp[6], ip[6]);
    dimin(dp[8], ip[8], dp[10], ip[10]);  dimin(dp[12], ip[12], dp[14], ip[14]);
    dimin(dp[0], ip[0], dp[4], ip[4]);    dimin(dp[8], ip[8], dp[12], ip[12]);
    dimin(dp[0], ip[0], dp[8], ip[8]);
    do_ = dp[0]; io_ = ip[0];
}

__device__ __forceinline__ void steer(float fx, float fy, float sx, float sy, float d2,
                                      float& ox, float& oy) {
    float dist = __fsqrt_rn(__fadd_rn(d2, 1e-12f));
    float q    = __fdiv_rn(5.0f, dist);
    float sc   = (dist > 5.0f) ? q : 1.0f;
    ox = __fadd_rn(fx, __fmul_rn(__fadd_rn(sx, -fx), sc));
    oy = __fadd_rn(fy, __fmul_rn(__fadd_rn(sy, -fy), sc));
}

__device__ __forceinline__ float d2_rn(float nx, float ny, float sx, float sy) {
    float dx = __fadd_rn(nx, -sx), dy = __fadd_rn(ny, -sy);
    return __fadd_rn(__fmul_rn(dx, dx), __fmul_rn(dy, dy));
}

// per-lane scan partial, 128-node tiles; sentinels/races benign (u64 keys exact)
__device__ __forceinline__ ull scan_part(const float2* __restrict__ nodes_s, float2 s,
                                         int bound, int t0, int tstep, int lane) {
    const float INF = __int_as_float(0x7f800000);
    float bd2 = INF; int bidx = 0;
    for (int t = t0; 128 * t <= bound; t += tstep) {
        int i0 = 128 * t + 2 * lane;
        float4 a = *reinterpret_cast<const float4*>(&nodes_s[i0]);
        float4 c = *reinterpret_cast<const float4*>(&nodes_s[i0 + 64]);
        float da0 = d2_rn(a.x, a.y, s.x, s.y);
        float da1 = d2_rn(a.z, a.w, s.x, s.y);
        float dc0 = d2_rn(c.x, c.y, s.x, s.y);
        float dc1 = d2_rn(c.z, c.w, s.x, s.y);
        float ma = fminf(da0, da1); int ia = (da0 <= da1) ? i0 : i0 + 1;
        float mc = fminf(dc0, dc1); int ic = (dc0 <= dc1) ? i0 + 64 : i0 + 65;
        float m  = fminf(ma, mc);   int mi = (ma <= mc) ? ia : ic;
        if (m < bd2) { bd2 = m; bidx = mi; }
    }
    return ((ull)__float_as_uint(bd2) << 32) | (uint32_t)bidx;
}

__global__ void __launch_bounds__(NTHREADS, 1) __cluster_dims__(CSIZE, 1, 1)
rrt_kernel(const float* __restrict__ state,
           const float* __restrict__ goal,
           const float* __restrict__ u,
           const float* __restrict__ r,
           float* __restrict__ out)
{
    extern __shared__ char smem_raw[];
    float2* nodes_s = (float2*)smem_raw;
    float2* samps   = (float2*)(smem_raw + OFF_SAMPS);
    ull (*bests)[CSIZE][NSLOT_PAD] = (ull (*)[CSIZE][NSLOT_PAD])(smem_raw + OFF_BESTS);
    float2* cand    = (float2*)(smem_raw + OFF_CAND);   // [2][32] ring
    ull* mbars      = (ull*)(smem_raw + OFF_MBARS);

    const int tid  = threadIdx.x;
    const int lane = tid & 31;
    const int warp = tid >> 5;
    const uint32_t crank = my_ctarank();
    const float INF = __int_as_float(0x7f800000);

    const uint32_t mb_nodes0 = smem_u32(&mbars[0]);   // 4 ring objs at +8*idx
    const uint32_t mb_bests0 = smem_u32(&mbars[4]);   // 4 objs at +8*idx

    // ---- init ----
    for (int i = tid; i < NODES_PAD; i += NTHREADS)
        nodes_s[i] = make_float2(INF, INF);
    const float gx = goal[0], gy = goal[1];
    for (int i = tid; i < MAX_ITER; i += NTHREADS) {
        float ui = u[i];
        float sx = __fmul_rn(r[2 * i],     200.0f);
        float sy = __fmul_rn(r[2 * i + 1], 200.0f);
        if (ui < 0.1f) { sx = gx; sy = gy; }
        samps[i] = make_float2(sx, sy);
    }
    if (tid < 64) cand[tid] = make_float2(INF, INF);   // blocks "-2","-1"
    if (tid == 0) {
        float2 st0 = make_float2(state[0], state[1]);
        nodes_s[0] = st0;
        // block "-1" ring half = parity 1; slot 31 <-> idx 32*0-31+31 = 0 = root
        cand[32 + 31] = st0;
        for (int o = 0; o < 4; o++) {
            mbar_init(mb_nodes0 + 8 * o, 32);          // serial warp lanes
            mbar_init(mb_bests0 + 8 * o, 33 * CSIZE);  // 33 slots x 8 src CTAs
        }
    }
    __syncthreads();
    CLUSTER_ARRIVE();
    CLUSTER_WAIT();

    for (int b = 0; b < NBLK; b++) {
        if (warp == SERIAL_WARP) {
            // ===== serial warp: fully self-sufficient block b =====
            const float2 s2 = samps[32 * b + lane];
            const float sx = s2.x, sy = s2.y;

            // ---- bests(b): [0, 32b-64], sent at iteration b-2 (fast-path wait) ----
            ull bk = KEY_INF;
            if (b >= 2) {
                const int obj = (b - 2) & 3;
                mbar_wait_cluster(mb_bests0 + 8 * obj, ((b - 2) >> 2) & 1);
                ull k0 = bests[obj][0][lane], k1 = bests[obj][1][lane];
                ull k2 = bests[obj][2][lane], k3 = bests[obj][3][lane];
                ull k4 = bests[obj][4][lane], k5 = bests[obj][5][lane];
                ull k6 = bests[obj][6][lane], k7 = bests[obj][7][lane];
                bk = umin64(umin64(umin64(k0, k1), umin64(k2, k3)),
                            umin64(umin64(k4, k5), umin64(k6, k7)));
                if (lane == 31) {                       // sample-31 second half
                    ull m0 = bests[obj][0][32], m1 = bests[obj][1][32];
                    ull m2 = bests[obj][2][32], m3 = bests[obj][3][32];
                    ull m4 = bests[obj][4][32], m5 = bests[obj][5][32];
                    ull m6 = bests[obj][6][32], m7 = bests[obj][7][32];
                    ull bk2 = umin64(umin64(umin64(m0, m1), umin64(m2, m3)),
                                     umin64(umin64(m4, m5), umin64(m6, m7)));
                    bk = umin64(bk, bk2);
                }
            }

            // ---- delta64 over cand ring: 16 float4s per half, depth-4 trees ----
            // old half = block b-2 (parity b&1, base 32b-63), new half = block b-1
            float dD; int iD;
            {
                const float4* oldh = (const float4*)(cand + 32 * (b & 1));
                const float4* newh = (const float4*)(cand + 32 * ((b - 1) & 1));
                float dp[16]; int ip[16];
                #pragma unroll
                for (int k = 0; k < 16; k++) {          // old half: 32 cands
                    float4 c = oldh[k];
                    float e0 = d2_rn(c.x, c.y, sx, sy);
                    float e1 = d2_rn(c.z, c.w, sx, sy);
                    dp[k] = fminf(e0, e1);
                    ip[k] = (e0 <= e1) ? (32 * b - 63 + 2 * k) : (32 * b - 62 + 2 * k);
                }
                float dOld; int iOld;
                tree16(dp, ip, dOld, iOld);
                #pragma unroll
                for (int k = 0; k < 16; k++) {          // new half: 32 cands
                    float4 c = newh[k];
                    float e0 = d2_rn(c.x, c.y, sx, sy);
                    float e1 = d2_rn(c.z, c.w, sx, sy);
                    dp[k] = fminf(e0, e1);
                    ip[k] = (e0 <= e1) ? (32 * b - 31 + 2 * k) : (32 * b - 30 + 2 * k);
                }
                float dNew; int iNew;
                tree16(dp, ip, dNew, iNew);
                dD = dOld; iD = iOld;
                dimin(dD, iD, dNew, iNew);              // old (lower idx) first
            }
            // ---- merge bests (lower idx than delta => <= prefers bests on tie) ----
            float bd2 = dD; int bidx = iD;
            if (b >= 2) {
                float bkd2 = __uint_as_float((uint32_t)(bk >> 32));
                if (bkd2 <= dD) { bd2 = bkd2; bidx = (int)(uint32_t)bk; }
            }

            float2 f = nodes_s[bidx];
            float cx, cy;
            steer(f.x, f.y, sx, sy, bd2, cx, cy);

            // ---- speculative fixup; working buffer = ring half b&1 ----
            float2* wcand = cand + 32 * (b & 1);
            const float4* wcand4 = (const float4*)wcand;
            __syncwarp();                                // delta reads done
            while (true) {
                wcand[lane] = make_float2(cx, cy);
                __syncwarp();
                float dv[16]; int iv[16];
                #pragma unroll
                for (int k = 0; k < 16; k++) {           // masked pair-mins, 32 cands
                    float4 c = wcand4[k];
                    int l0 = 2 * k, l1 = 2 * k + 1;
                    float e0 = d2_rn(c.x, c.y, sx, sy);
                    float e1 = d2_rn(c.z, c.w, sx, sy);
                    e0 = (l0 < lane) ? e0 : INF;
                    e1 = (l1 < lane) ? e1 : INF;
                    dv[k] = fminf(e0, e1);
                    iv[k] = (e0 <= e1) ? l0 : l1;
                }
                float vmin; int vl;
                tree16(dv, iv, vmin, vl);
                unsigned mask = __ballot_sync(FULLMASK, vmin < bd2);   // strict <
                if (!mask) break;
                int F2 = __ffs((int)mask) - 1;           // first violator vs finals
                if (lane == F2) {
                    bd2 = vmin;
                    float2 c = wcand[vl];
                    steer(c.x, c.y, sx, sy, bd2, cx, cy);
                }
            }
            __syncwarp();
            nodes_s[32 * b + 1 + lane] = make_float2(cx, cy);
            if (b < NBLK - 1)
                mbar_arrive_cta(mb_nodes0 + 8 * (b & 3));   // all 32 lanes
        } else {
            // ===== scan warps (0..30): iteration j = b, entirely off-path =====
            const int j = b;
            if (j > NBLK - 3) continue;               // no consumer remains
            if (j >= 1)                               // nodes [0,32j] final
                mbar_wait_cta(mb_nodes0 + 8 * ((j - 1) & 3), ((j - 1) >> 2) & 1);

            const int obj = j & 3;                    // consumed by serial block j+2
            ull pk = scan_part(nodes_s, samps[32 * (j + 2) + warp],
                               32 * j, (int)crank, CSIZE, lane);
            pk = bfly_min(pk);
            if (lane < CSIZE) {
                uint32_t la = smem_u32(&bests[obj][crank][warp]);
                st_cluster_u64(mapa_u32(la, (uint32_t)lane), pk);
                mbar_arrive_cluster_remote(mapa_u32(mb_bests0 + 8 * obj, (uint32_t)lane));
            }
            if (warp == 29 || warp == 30) {           // sample-31 scan split halves
                int t0 = (warp == 29) ? (int)crank : (int)crank + CSIZE;
                ull pk2 = scan_part(nodes_s, samps[32 * (j + 2) + 31],
                                    32 * j, t0, 2 * CSIZE, lane);
                pk2 = bfly_min(pk2);
                int slot = (warp == 29) ? 31 : 32;
                if (lane < CSIZE) {
                    uint32_t la = smem_u32(&bests[obj][crank][slot]);
                    st_cluster_u64(mapa_u32(la, (uint32_t)lane), pk2);
                    mbar_arrive_cluster_remote(mapa_u32(mb_bests0 + 8 * obj, (uint32_t)lane));
                }
            }
        }
    }

    __syncthreads();
    CLUSTER_ARRIVE();
    CLUSTER_WAIT();

    if (crank == 0) {
        const float* ns = reinterpret_cast<const float*>(nodes_s);
        for (int i = tid; i < 2 * NNODES; i += NTHREADS)
            out[i] = ns[i];
    }
}

extern "C" void kernel_launch(void* const* d_in, const int* in_sizes, int n_in,
                              void* d_out, int out_size)
{
    const float* state = (const float*)d_in[0];
    const float* goal  = (const float*)d_in[1];
    const float* u     = (const float*)d_in[2];
    const float* r     = (const float*)d_in[3];
    float* out = (float*)d_out;

    cudaFuncSetAttribute(rrt_kernel,
                         cudaFuncAttributeMaxDynamicSharedMemorySize,
                         (int)SMEM_BYTES);
    rrt_kernel<<<CSIZE, NTHREADS, SMEM_BYTES>>>(state, goal, u, r, out);
}

// round 14
// speedup vs baseline: 1.3852x; 1.0626x over previous
#include <cuda_runtime.h>
#include <cstdint>

typedef unsigned long long ull;
#define FULLMASK 0xffffffffu

constexpr int MAX_ITER = 8192;
constexpr int NNODES   = MAX_ITER + 1;   // 8193
constexpr int NBLK     = 256;            // 32 iterations per block
constexpr int NTHREADS = 1024;           // 32 warps
constexpr int CSIZE    = 8;
constexpr int SERIAL_WARP = 31;

constexpr int NODES_PAD = 8208;          // 8193 + sentinel pad (scan reads < 8208)
constexpr int NSLOT_PAD = 34;            // 0..30 samples, 31/32 = sample-31 halves

// per-CTA smem layout:
//   nodes float2[8208] | samps float2[8192] | bests ull[4][8][34]
//   stage ull[4][34] | cand float2[2][32]
//   mbars ull[12]: [0..3]=nodes ring, [4..7]=bests objs, [8..11]=free objs
constexpr size_t OFF_SAMPS = (size_t)NODES_PAD * sizeof(float2);
constexpr size_t OFF_BESTS = OFF_SAMPS + (size_t)MAX_ITER * sizeof(float2);
constexpr size_t OFF_STAGE = OFF_BESTS + 4ull * CSIZE * NSLOT_PAD * sizeof(ull);
constexpr size_t OFF_CAND  = OFF_STAGE + 4ull * NSLOT_PAD * sizeof(ull);
constexpr size_t OFF_MBARS = OFF_CAND + 64ull * sizeof(float2);
constexpr size_t SMEM_BYTES = OFF_MBARS + 12ull * sizeof(ull);

constexpr ull KEY_INF = ((ull)0x7f800000u << 32);

__device__ __forceinline__ uint32_t smem_u32(const void* p) {
    return (uint32_t)__cvta_generic_to_shared(p);
}
__device__ __forceinline__ uint32_t my_ctarank() {
    uint32_t r; asm("mov.u32 %0, %%cluster_ctarank;" : "=r"(r)); return r;
}
__device__ __forceinline__ uint32_t mapa_u32(uint32_t laddr, uint32_t rank) {
    uint32_t r; asm("mapa.shared::cluster.u32 %0, %1, %2;" : "=r"(r) : "r"(laddr), "r"(rank));
    return r;
}
__device__ __forceinline__ void mbar_init(uint32_t a, uint32_t cnt) {
    asm volatile("mbarrier.init.shared.b64 [%0], %1;" :: "r"(a), "r"(cnt) : "memory");
}
__device__ __forceinline__ void mbar_arrive_cta(uint32_t a) {
    asm volatile("mbarrier.arrive.release.cta.shared::cta.b64 _, [%0];" :: "r"(a) : "memory");
}
__device__ __forceinline__ void mbar_arrive_cluster_remote(uint32_t raddr) {
    asm volatile("mbarrier.arrive.release.cluster.shared::cluster.b64 _, [%0];"
                 :: "r"(raddr) : "memory");
}
__device__ __forceinline__ void mbar_wait_cta(uint32_t a, uint32_t phase) {
    asm volatile(
        "{\n\t.reg .pred P;\n\t"
        "WL_%=:\n\t"
        "mbarrier.try_wait.parity.acquire.cta.shared::cta.b64 P, [%0], %1, 0x989680;\n\t"
        "@P bra.uni WD_%=;\n\t"
        "bra.uni WL_%=;\n\t"
        "WD_%=:\n\t}"
        :: "r"(a), "r"(phase) : "memory");
}
__device__ __forceinline__ void mbar_wait_cluster(uint32_t a, uint32_t phase) {
    asm volatile(
        "{\n\t.reg .pred P;\n\t"
        "WL_%=:\n\t"
        "mbarrier.try_wait.parity.acquire.cluster.shared::cta.b64 P, [%0], %1, 0x989680;\n\t"
        "@P bra.uni WD_%=;\n\t"
        "bra.uni WL_%=;\n\t"
        "WD_%=:\n\t}"
        :: "r"(a), "r"(phase) : "memory");
}
#define CLUSTER_ARRIVE() asm volatile("barrier.cluster.arrive.aligned;" ::: "memory")
#define CLUSTER_WAIT()   asm volatile("barrier.cluster.wait.aligned;"   ::: "memory")
#define SCAN_BAR()       asm volatile("bar.sync 1, 992;" ::: "memory")

__device__ __forceinline__ ull bfly_min(ull key) {
    #pragma unroll
    for (int o = 16; o > 0; o >>= 1) {
        ull other = __shfl_xor_sync(FULLMASK, key, o);
        key = (other < key) ? other : key;
    }
    return key;
}

__device__ __forceinline__ void steer(float fx, float fy, float sx, float sy, float d2,
                                      float& ox, float& oy) {
    float dist = __fsqrt_rn(__fadd_rn(d2, 1e-12f));
    float q    = __fdiv_rn(5.0f, dist);
    float sc   = (dist > 5.0f) ? q : 1.0f;
    ox = __fadd_rn(fx, __fmul_rn(__fadd_rn(sx, -fx), sc));
    oy = __fadd_rn(fy, __fmul_rn(__fadd_rn(sy, -fy), sc));
}

__device__ __forceinline__ float d2_rn(float nx, float ny, float sx, float sy) {
    float dx = __fadd_rn(nx, -sx), dy = __fadd_rn(ny, -sy);
    return __fadd_rn(__fmul_rn(dx, dx), __fmul_rn(dy, dy));
}

// per-lane scan partial, 128-node tiles; sentinels/races benign (u64 keys exact)
__device__ __forceinline__ ull scan_part(const float2* __restrict__ nodes_s, float2 s,
                                         int bound, int t0, int tstep, int lane) {
    const float INF = __int_as_float(0x7f800000);
    float bd2 = INF; int bidx = 0;
    for (int t = t0; 128 * t <= bound; t += tstep) {
        int i0 = 128 * t + 2 * lane;
        float4 a = *reinterpret_cast<const float4*>(&nodes_s[i0]);
        float4 c = *reinterpret_cast<const float4*>(&nodes_s[i0 + 64]);
        float da0 = d2_rn(a.x, a.y, s.x, s.y);
        float da1 = d2_rn(a.z, a.w, s.x, s.y);
        float dc0 = d2_rn(c.x, c.y, s.x, s.y);
        float dc1 = d2_rn(c.z, c.w, s.x, s.y);
        float ma = fminf(da0, da1); int ia = (da0 <= da1) ? i0 : i0 + 1;
        float mc = fminf(dc0, dc1); int ic = (dc0 <= dc1) ? i0 + 64 : i0 + 65;
        float m  = fminf(ma, mc);   int mi = (ma <= mc) ? ia : ic;
        if (m < bd2) { bd2 = m; bidx = mi; }
    }
    return ((ull)__float_as_uint(bd2) << 32) | (uint32_t)bidx;
}

__global__ void __launch_bounds__(NTHREADS, 1) __cluster_dims__(CSIZE, 1, 1)
rrt_kernel(const float* __restrict__ state,
           const float* __restrict__ goal,
           const float* __restrict__ u,
           const float* __restrict__ r,
           float* __restrict__ out)
{
    extern __shared__ char smem_raw[];
    float2* nodes_s = (float2*)smem_raw;
    float2* samps   = (float2*)(smem_raw + OFF_SAMPS);
    ull (*bests)[CSIZE][NSLOT_PAD] = (ull (*)[CSIZE][NSLOT_PAD])(smem_raw + OFF_BESTS);
    ull (*stage)[NSLOT_PAD] = (ull (*)[NSLOT_PAD])(smem_raw + OFF_STAGE);
    float2* cand    = (float2*)(smem_raw + OFF_CAND);   // [2][32] ring
    ull* mbars      = (ull*)(smem_raw + OFF_MBARS);

    const int tid  = threadIdx.x;
    const int lane = tid & 31;
    const int warp = tid >> 5;
    const uint32_t crank = my_ctarank();
    const float INF = __int_as_float(0x7f800000);

    const uint32_t mb_nodes0 = smem_u32(&mbars[0]);   // 4 ring objs at +8*idx
    const uint32_t mb_bests0 = smem_u32(&mbars[4]);   // 4 objs at +8*idx
    const uint32_t mb_free0  = smem_u32(&mbars[8]);   // 4 objs at +8*idx

    // ---- init ----
    for (int i = tid; i < NODES_PAD; i += NTHREADS)
        nodes_s[i] = make_float2(INF, INF);
    const float gx = goal[0], gy = goal[1];
    for (int i = tid; i < MAX_ITER; i += NTHREADS) {
        float ui = u[i];
        float sx = __fmul_rn(r[2 * i],     200.0f);
        float sy = __fmul_rn(r[2 * i + 1], 200.0f);
        if (ui < 0.1f) { sx = gx; sy = gy; }
        samps[i] = make_float2(sx, sy);
    }
    if (tid < 64) cand[tid] = make_float2(INF, INF);   // blocks "-2","-1"
    if (tid < 4 * NSLOT_PAD) ((ull*)stage)[tid] = KEY_INF;
    if (tid == 0) {
        float2 st0 = make_float2(state[0], state[1]);
        nodes_s[0] = st0;
        // block "-1" ring half = parity 1; slot 31 <-> idx 32*0-31+31 = 0 = root
        cand[32 + 31] = st0;
        for (int o = 0; o < 4; o++) {
            mbar_init(mb_nodes0 + 8 * o, 32);          // serial warp lanes
            mbar_init(mb_bests0 + 8 * o, CSIZE);       // ONE arrive per src CTA
            mbar_init(mb_free0  + 8 * o, CSIZE);       // one arrive per dst serial
        }
    }
    __syncthreads();
    CLUSTER_ARRIVE();
    CLUSTER_WAIT();

    for (int b = 0; b < NBLK; b++) {
        if (warp == SERIAL_WARP) {
            // ===== serial warp: fully self-sufficient block b (R9-exact math) =====
            const float2 s2 = samps[32 * b + lane];
            const float sx = s2.x, sy = s2.y;

            // delta64 over cand ring: older half (block b-2, parity b&1, base 32b-63)
            // then newer half (block b-1, base 32b-31); increasing idx + strict <
            float bd2 = INF; int bidx = 0;
            {
                const float4* oldh = (const float4*)(cand + 32 * (b & 1));
                const float4* newh = (const float4*)(cand + 32 * ((b - 1) & 1));
                #pragma unroll
                for (int l = 0; l < 32; l += 2) {
                    float4 c = oldh[l >> 1];
                    float d0 = d2_rn(c.x, c.y, sx, sy);
                    float d1 = d2_rn(c.z, c.w, sx, sy);
                    if (d0 < bd2) { bd2 = d0; bidx = 32 * b - 63 + l; }
                    if (d1 < bd2) { bd2 = d1; bidx = 32 * b - 63 + l + 1; }
                }
                #pragma unroll
                for (int l = 0; l < 32; l += 2) {
                    float4 c = newh[l >> 1];
                    float d0 = d2_rn(c.x, c.y, sx, sy);
                    float d1 = d2_rn(c.z, c.w, sx, sy);
                    if (d0 < bd2) { bd2 = d0; bidx = 32 * b - 31 + l; }
                    if (d1 < bd2) { bd2 = d1; bidx = 32 * b - 31 + l + 1; }
                }
            }
            // merge bests(b): [0, 32b-64], sent at iteration b-2 (2 blocks slack)
            if (b >= 2) {
                const int obj = (b - 2) & 3;
                mbar_wait_cluster(mb_bests0 + 8 * obj, ((b - 2) >> 2) & 1);
                ull kk = KEY_INF;
                #pragma unroll
                for (int c = 0; c < CSIZE; c++) {
                    ull k2 = bests[obj][c][lane];
                    kk = (k2 < kk) ? k2 : kk;
                }
                if (lane == 31) {
                    #pragma unroll
                    for (int c = 0; c < CSIZE; c++) {
                        ull k2 = bests[obj][c][32];
                        kk = (k2 < kk) ? k2 : kk;
                    }
                }
                // release bests[obj] for reuse: one arrive to EVERY CTA's free[obj]
                if (lane < CSIZE)
                    mbar_arrive_cluster_remote(mapa_u32(mb_free0 + 8 * obj,
                                                        (uint32_t)lane));
                ull dk = ((ull)__float_as_uint(bd2) << 32) | (uint32_t)bidx;
                if (kk < dk) {                       // u64: exact (d2, idx) order
                    bd2  = __uint_as_float((uint32_t)(kk >> 32));
                    bidx = (int)(uint32_t)kk;
                }
            }
            float2 f = nodes_s[bidx];
            float cx, cy;
            steer(f.x, f.y, sx, sy, bd2, cx, cy);

            // speculative fixup; working buffer = ring half b&1 (old data consumed)
            float2* wcand = cand + 32 * (b & 1);
            const float4* wcand4 = (const float4*)wcand;
            __syncwarp();                            // delta reads done before overwrite
            while (true) {
                wcand[lane] = make_float2(cx, cy);
                __syncwarp();
                float vmin = INF; int vl = 0;
                #pragma unroll
                for (int l = 0; l < 32; l += 2) {
                    float4 c = wcand4[l >> 1];
                    float e0 = d2_rn(c.x, c.y, sx, sy);
                    float e1 = d2_rn(c.z, c.w, sx, sy);
                    if (l     < lane && e0 < vmin) { vmin = e0; vl = l; }
                    if (l + 1 < lane && e1 < vmin) { vmin = e1; vl = l + 1; }
                }
                unsigned mask = __ballot_sync(FULLMASK, vmin < bd2);   // strict <
                if (!mask) break;
                int F2 = __ffs((int)mask) - 1;       // first violator vs finals only
                if (lane == F2) {
                    bd2 = vmin;
                    float2 c = wcand[vl];
                    steer(c.x, c.y, sx, sy, bd2, cx, cy);
                }
            }
            __syncwarp();
            nodes_s[32 * b + 1 + lane] = make_float2(cx, cy);
            if (b < NBLK - 1)
                mbar_arrive_cta(mb_nodes0 + 8 * (b & 3));   // all 32 lanes
        } else {
            // ===== scan warps (0..30): iteration j = b, entirely off-path =====
            const int j = b;
            if (j > NBLK - 3) continue;               // no consumer remains
            if (j >= 1)                               // nodes [0,32j] final
                mbar_wait_cta(mb_nodes0 + 8 * ((j - 1) & 3), ((j - 1) >> 2) & 1);

            const int obj = j & 3;                    // consumed by serial block j+2
            ull pk = scan_part(nodes_s, samps[32 * (j + 2) + warp],
                               32 * j, (int)crank, CSIZE, lane);
            pk = bfly_min(pk);
            if (lane == 0) stage[obj][warp] = pk;     // local staging
            if (warp == 29 || warp == 30) {           // sample-31 scan split halves
                int t0 = (warp == 29) ? (int)crank : (int)crank + CSIZE;
                ull pk2 = scan_part(nodes_s, samps[32 * (j + 2) + 31],
                                    32 * j, t0, 2 * CSIZE, lane);
                pk2 = bfly_min(pk2);
                int slot = (warp == 29) ? 31 : 32;
                if (lane == 0) stage[obj][slot] = pk2;
            }
            SCAN_BAR();                               // 31 scan warps: staging visible

            // ---- batched cross-CTA send: warp w (w<8) -> CTA w, lane 0 only ----
            if (warp < CSIZE && lane == 0) {
                // backpressure: previous readers of bests[obj] (all dst serials
                // at their block j-2) must have finished before we overwrite
                if (j >= 4)
                    mbar_wait_cluster(mb_free0 + 8 * obj, ((j - 4) >> 2) & 1);
                uint32_t src  = smem_u32(&stage[obj][0]);
                uint32_t dstr = mapa_u32(smem_u32(&bests[obj][crank][0]),
                                         (uint32_t)warp);
                #pragma unroll
                for (int k = 0; k < 17; k++) {        // 34 slots = 17 x 16B
                    ull a0, a1;
                    asm volatile("ld.shared.v2.u64 {%0, %1}, [%2];"
                                 : "=l"(a0), "=l"(a1) : "r"(src + 16 * k));
                    asm volatile("st.shared::cluster.v2.u64 [%0], {%1, %2};"
                                 :: "r"(dstr + 16 * k), "l"(a0), "l"(a1) : "memory");
                }
                mbar_arrive_cluster_remote(mapa_u32(mb_bests0 + 8 * obj,
                                                    (uint32_t)warp));
            }
        }
    }

    __syncthreads();
    CLUSTER_ARRIVE();
    CLUSTER_WAIT();

    if (crank == 0) {
        const float* ns = reinterpret_cast<const float*>(nodes_s);
        for (int i = tid; i < 2 * NNODES; i += NTHREADS)
            out[i] = ns[i];
    }
}

extern "C" void kernel_launch(void* const* d_in, const int* in_sizes, int n_in,
                              void* d_out, int out_size)
{
    const float* state = (const float*)d_in[0];
    const float* goal  = (const float*)d_in[1];
    const float* u     = (const float*)d_in[2];
    const float* r     = (const float*)d_in[3];
    float* out = (float*)d_out;

    cudaFuncSetAttribute(rrt_kernel,
                         cudaFuncAttributeMaxDynamicSharedMemorySize,
                         (int)SMEM_BYTES);
    rrt_kernel<<<CSIZE, NTHREADS, SMEM_BYTES>>>(state, goal, u, r, out);
}

// round 15
// speedup vs baseline: 1.4471x; 1.0447x over previous
#include <cuda_runtime.h>
#include <cstdint>

typedef unsigned long long ull;
#define FULLMASK 0xffffffffu

constexpr int MAX_ITER = 8192;
constexpr int NNODES   = MAX_ITER + 1;   // 8193
constexpr int NBLK     = 256;            // 32 iterations per block
constexpr int NTHREADS = 1024;           // 32 warps
constexpr int CSIZE    = 8;
constexpr int SERIAL_WARP = 31;

constexpr int NODES_PAD = 8208;          // 8193 + sentinel pad (scan reads < 8208)
constexpr int NSLOT_PAD = 34;            // 0..30 samples, 31/32 = sample-31 halves

// per-CTA smem layout:
//   nodes float2[8208] | samps float2[8192] | bests ull[4][8][34]
//   stage ull[4][34] | cand float2[2][32]
//   mbars ull[12]: [0..3]=nodes ring, [4..7]=bests objs, [8..11]=free objs
constexpr size_t OFF_SAMPS = (size_t)NODES_PAD * sizeof(float2);
constexpr size_t OFF_BESTS = OFF_SAMPS + (size_t)MAX_ITER * sizeof(float2);
constexpr size_t OFF_STAGE = OFF_BESTS + 4ull * CSIZE * NSLOT_PAD * sizeof(ull);
constexpr size_t OFF_CAND  = OFF_STAGE + 4ull * NSLOT_PAD * sizeof(ull);
constexpr size_t OFF_MBARS = OFF_CAND + 64ull * sizeof(float2);
constexpr size_t SMEM_BYTES = OFF_MBARS + 12ull * sizeof(ull);

constexpr ull KEY_INF = ((ull)0x7f800000u << 32);

__device__ __forceinline__ uint32_t smem_u32(const void* p) {
    return (uint32_t)__cvta_generic_to_shared(p);
}
__device__ __forceinline__ uint32_t my_ctarank() {
    uint32_t r; asm("mov.u32 %0, %%cluster_ctarank;" : "=r"(r)); return r;
}
__device__ __forceinline__ uint32_t mapa_u32(uint32_t laddr, uint32_t rank) {
    uint32_t r; asm("mapa.shared::cluster.u32 %0, %1, %2;" : "=r"(r) : "r"(laddr), "r"(rank));
    return r;
}
__device__ __forceinline__ void mbar_init(uint32_t a, uint32_t cnt) {
    asm volatile("mbarrier.init.shared.b64 [%0], %1;" :: "r"(a), "r"(cnt) : "memory");
}
__device__ __forceinline__ void mbar_arrive_cta(uint32_t a) {
    asm volatile("mbarrier.arrive.release.cta.shared::cta.b64 _, [%0];" :: "r"(a) : "memory");
}
__device__ __forceinline__ void mbar_arrive_cluster_remote(uint32_t raddr) {
    asm volatile("mbarrier.arrive.release.cluster.shared::cluster.b64 _, [%0];"
                 :: "r"(raddr) : "memory");
}
__device__ __forceinline__ void mbar_wait_cta(uint32_t a, uint32_t phase) {
    asm volatile(
        "{\n\t.reg .pred P;\n\t"
        "WL_%=:\n\t"
        "mbarrier.try_wait.parity.acquire.cta.shared::cta.b64 P, [%0], %1, 0x989680;\n\t"
        "@P bra.uni WD_%=;\n\t"
        "bra.uni WL_%=;\n\t"
        "WD_%=:\n\t}"
        :: "r"(a), "r"(phase) : "memory");
}
__device__ __forceinline__ void mbar_wait_cluster(uint32_t a, uint32_t phase) {
    asm volatile(
        "{\n\t.reg .pred P;\n\t"
        "WL_%=:\n\t"
        "mbarrier.try_wait.parity.acquire.cluster.shared::cta.b64 P, [%0], %1, 0x989680;\n\t"
        "@P bra.uni WD_%=;\n\t"
        "bra.uni WL_%=;\n\t"
        "WD_%=:\n\t}"
        :: "r"(a), "r"(phase) : "memory");
}
#define CLUSTER_ARRIVE() asm volatile("barrier.cluster.arrive.aligned;" ::: "memory")
#define CLUSTER_WAIT()   asm volatile("barrier.cluster.wait.aligned;"   ::: "memory")
#define SCAN_BAR()       asm volatile("bar.sync 1, 992;" ::: "memory")

__device__ __forceinline__ ull bfly_min(ull key) {
    #pragma unroll
    for (int o = 16; o > 0; o >>= 1) {
        ull other = __shfl_xor_sync(FULLMASK, key, o);
        key = (other < key) ? other : key;
    }
    return key;
}

__device__ __forceinline__ void steer(float fx, float fy, float sx, float sy, float d2,
                                      float& ox, float& oy) {
    float dist = __fsqrt_rn(__fadd_rn(d2, 1e-12f));
    float q    = __fdiv_rn(5.0f, dist);
    float sc   = (dist > 5.0f) ? q : 1.0f;
    ox = __fadd_rn(fx, __fmul_rn(__fadd_rn(sx, -fx), sc));
    oy = __fadd_rn(fy, __fmul_rn(__fadd_rn(sy, -fy), sc));
}

__device__ __forceinline__ float d2_rn(float nx, float ny, float sx, float sy) {
    float dx = __fadd_rn(nx, -sx), dy = __fadd_rn(ny, -sy);
    return __fadd_rn(__fmul_rn(dx, dx), __fmul_rn(dy, dy));
}

// packed f32x2 distance: per-component IEEE rn => bit-identical to d2_rn
__device__ __forceinline__ float d2_pk(float nx, float ny, ull ns_pk) {
    ull nxy;  asm("mov.b64 %0, {%1, %2};" : "=l"(nxy) : "r"(__float_as_uint(nx)),
                                                        "r"(__float_as_uint(ny)));
    ull diff; asm("add.rn.f32x2 %0, %1, %2;" : "=l"(diff) : "l"(nxy), "l"(ns_pk));
    ull sq;   asm("mul.rn.f32x2 %0, %1, %2;" : "=l"(sq)   : "l"(diff), "l"(diff));
    uint32_t lo, hi;
    asm("mov.b64 {%0, %1}, %2;" : "=r"(lo), "=r"(hi) : "l"(sq));
    return __fadd_rn(__uint_as_float(lo), __uint_as_float(hi));
}

// per-lane scan partial, 128-node tiles t = t0, t0+tstep, ... while 128t <= bound.
// Loop tracks only the winning TILE (strict < => earliest tile on ties); the
// winning tile is recomputed once afterwards with the exact first-index
// tiebreak. Monotonic sentinel->final writes make raced keys TRUE (d2,idx)
// pairs that duplicate delta/P coverage, so the u64 lexicographic merge
// downstream remains exact.
__device__ __forceinline__ ull scan_part(const float2* __restrict__ nodes_s, float2 s,
                                         int bound, int t0, int tstep, int lane) {
    const float INF = __int_as_float(0x7f800000);
    ull ns_pk;   // (-sx, -sy) packed
    asm("mov.b64 %0, {%1, %2};" : "=l"(ns_pk)
        : "r"(__float_as_uint(-s.x)), "r"(__float_as_uint(-s.y)));
    float bd2 = INF; int btile = -1;
    #pragma unroll 2
    for (int t = t0; 128 * t <= bound; t += tstep) {
        int i0 = 128 * t + 2 * lane;
        float4 a = *reinterpret_cast<const float4*>(&nodes_s[i0]);
        float4 c = *reinterpret_cast<const float4*>(&nodes_s[i0 + 64]);
        float da0 = d2_pk(a.x, a.y, ns_pk);
        float da1 = d2_pk(a.z, a.w, ns_pk);
        float dc0 = d2_pk(c.x, c.y, ns_pk);
        float dc1 = d2_pk(c.z, c.w, ns_pk);
        float m = fminf(fminf(da0, da1), fminf(dc0, dc1));
        if (m < bd2) { bd2 = m; btile = t; }     // strict <: earliest tile
    }
    int bidx = 0;
    if (btile >= 0) {
        int i0 = 128 * btile + 2 * lane;
        float4 a = *reinterpret_cast<const float4*>(&nodes_s[i0]);
        float4 c = *reinterpret_cast<const float4*>(&nodes_s[i0 + 64]);
        float da0 = d2_pk(a.x, a.y, ns_pk);
        float da1 = d2_pk(a.z, a.w, ns_pk);
        float dc0 = d2_pk(c.x, c.y, ns_pk);
        float dc1 = d2_pk(c.z, c.w, ns_pk);
        float m01 = fminf(da0, da1); int i01 = (da0 <= da1) ? i0 : i0 + 1;
        float m23 = fminf(dc0, dc1); int i23 = (dc0 <= dc1) ? i0 + 64 : i0 + 65;
        bd2  = fminf(m01, m23);
        bidx = (m01 <= m23) ? i01 : i23;         // lower idx on tie
    }
    return ((ull)__float_as_uint(bd2) << 32) | (uint32_t)bidx;
}

__global__ void __launch_bounds__(NTHREADS, 1) __cluster_dims__(CSIZE, 1, 1)
rrt_kernel(const float* __restrict__ state,
           const float* __restrict__ goal,
           const float* __restrict__ u,
           const float* __restrict__ r,
           float* __restrict__ out)
{
    extern __shared__ char smem_raw[];
    float2* nodes_s = (float2*)smem_raw;
    float2* samps   = (float2*)(smem_raw + OFF_SAMPS);
    ull (*bests)[CSIZE][NSLOT_PAD] = (ull (*)[CSIZE][NSLOT_PAD])(smem_raw + OFF_BESTS);
    ull (*stage)[NSLOT_PAD] = (ull (*)[NSLOT_PAD])(smem_raw + OFF_STAGE);
    float2* cand    = (float2*)(smem_raw + OFF_CAND);   // [2][32] ring
    ull* mbars      = (ull*)(smem_raw + OFF_MBARS);

    const int tid  = threadIdx.x;
    const int lane = tid & 31;
    const int warp = tid >> 5;
    const uint32_t crank = my_ctarank();
    const float INF = __int_as_float(0x7f800000);

    const uint32_t mb_nodes0 = smem_u32(&mbars[0]);   // 4 ring objs at +8*idx
    const uint32_t mb_bests0 = smem_u32(&mbars[4]);   // 4 objs at +8*idx
    const uint32_t mb_free0  = smem_u32(&mbars[8]);   // 4 objs at +8*idx

    // ---- init ----
    for (int i = tid; i < NODES_PAD; i += NTHREADS)
        nodes_s[i] = make_float2(INF, INF);
    const float gx = goal[0], gy = goal[1];
    for (int i = tid; i < MAX_ITER; i += NTHREADS) {
        float ui = u[i];
        float sx = __fmul_rn(r[2 * i],     200.0f);
        float sy = __fmul_rn(r[2 * i + 1], 200.0f);
        if (ui < 0.1f) { sx = gx; sy = gy; }
        samps[i] = make_float2(sx, sy);
    }
    if (tid < 64) cand[tid] = make_float2(INF, INF);   // blocks "-2","-1"
    if (tid < 4 * NSLOT_PAD) ((ull*)stage)[tid] = KEY_INF;
    if (tid == 0) {
        float2 st0 = make_float2(state[0], state[1]);
        nodes_s[0] = st0;
        // block "-1" ring half = parity 1; slot 31 <-> idx 32*0-31+31 = 0 = root
        cand[32 + 31] = st0;
        for (int o = 0; o < 4; o++) {
            mbar_init(mb_nodes0 + 8 * o, 32);          // serial warp lanes
            mbar_init(mb_bests0 + 8 * o, CSIZE);       // ONE arrive per src CTA
            mbar_init(mb_free0  + 8 * o, CSIZE);       // one arrive per dst serial
        }
    }
    __syncthreads();
    CLUSTER_ARRIVE();
    CLUSTER_WAIT();

    for (int b = 0; b < NBLK; b++) {
        if (warp == SERIAL_WARP) {
            // ===== serial warp: fully self-sufficient block b (R9-exact math) =====
            const float2 s2 = samps[32 * b + lane];
            const float sx = s2.x, sy = s2.y;

            // delta64 over cand ring: older half (block b-2, parity b&1, base 32b-63)
            // then newer half (block b-1, base 32b-31); increasing idx + strict <
            float bd2 = INF; int bidx = 0;
            {
                const float4* oldh = (const float4*)(cand + 32 * (b & 1));
                const float4* newh = (const float4*)(cand + 32 * ((b - 1) & 1));
                #pragma unroll
                for (int l = 0; l < 32; l += 2) {
                    float4 c = oldh[l >> 1];
                    float d0 = d2_rn(c.x, c.y, sx, sy);
                    float d1 = d2_rn(c.z, c.w, sx, sy);
                    if (d0 < bd2) { bd2 = d0; bidx = 32 * b - 63 + l; }
                    if (d1 < bd2) { bd2 = d1; bidx = 32 * b - 63 + l + 1; }
                }
                #pragma unroll
                for (int l = 0; l < 32; l += 2) {
                    float4 c = newh[l >> 1];
                    float d0 = d2_rn(c.x, c.y, sx, sy);
                    float d1 = d2_rn(c.z, c.w, sx, sy);
                    if (d0 < bd2) { bd2 = d0; bidx = 32 * b - 31 + l; }
                    if (d1 < bd2) { bd2 = d1; bidx = 32 * b - 31 + l + 1; }
                }
            }
            // merge bests(b): [0, 32b-64], sent at iteration b-2 (2 blocks slack)
            if (b >= 2) {
                const int obj = (b - 2) & 3;
                mbar_wait_cluster(mb_bests0 + 8 * obj, ((b - 2) >> 2) & 1);
                ull kk = KEY_INF;
                #pragma unroll
                for (int c = 0; c < CSIZE; c++) {
                    ull k2 = bests[obj][c][lane];
                    kk = (k2 < kk) ? k2 : kk;
                }
                if (lane == 31) {
                    #pragma unroll
                    for (int c = 0; c < CSIZE; c++) {
                        ull k2 = bests[obj][c][32];
                        kk = (k2 < kk) ? k2 : kk;
                    }
                }
                // release bests[obj] for reuse: one arrive to EVERY CTA's free[obj]
                if (lane < CSIZE)
                    mbar_arrive_cluster_remote(mapa_u32(mb_free0 + 8 * obj,
                                                        (uint32_t)lane));
                ull dk = ((ull)__float_as_uint(bd2) << 32) | (uint32_t)bidx;
                if (kk < dk) {                       // u64: exact (d2, idx) order
                    bd2  = __uint_as_float((uint32_t)(kk >> 32));
                    bidx = (int)(uint32_t)kk;
                }
            }
            float2 f = nodes_s[bidx];
            float cx, cy;
            steer(f.x, f.y, sx, sy, bd2, cx, cy);

            // speculative fixup; working buffer = ring half b&1 (old data consumed)
            float2* wcand = cand + 32 * (b & 1);
            const float4* wcand4 = (const float4*)wcand;
            __syncwarp();                            // delta reads done before overwrite
            while (true) {
                wcand[lane] = make_float2(cx, cy);
                __syncwarp();
                float vmin = INF; int vl = 0;
                #pragma unroll
                for (int l = 0; l < 32; l += 2) {
                    float4 c = wcand4[l >> 1];
                    float e0 = d2_rn(c.x, c.y, sx, sy);
                    float e1 = d2_rn(c.z, c.w, sx, sy);
                    if (l     < lane && e0 < vmin) { vmin = e0; vl = l; }
                    if (l + 1 < lane && e1 < vmin) { vmin = e1; vl = l + 1; }
                }
                unsigned mask = __ballot_sync(FULLMASK, vmin < bd2);   // strict <
                if (!mask) break;
                int F2 = __ffs((int)mask) - 1;       // first violator vs finals only
                if (lane == F2) {
                    bd2 = vmin;
                    float2 c = wcand[vl];
                    steer(c.x, c.y, sx, sy, bd2, cx, cy);
                }
            }
            __syncwarp();
            nodes_s[32 * b + 1 + lane] = make_float2(cx, cy);
            if (b < NBLK - 1)
                mbar_arrive_cta(mb_nodes0 + 8 * (b & 3));   // all 32 lanes
        } else {
            // ===== scan warps (0..30): iteration j = b, entirely off-path =====
            const int j = b;
            if (j > NBLK - 3) continue;               // no consumer remains
            if (j >= 1)                               // nodes [0,32j] final
                mbar_wait_cta(mb_nodes0 + 8 * ((j - 1) & 3), ((j - 1) >> 2) & 1);

            const int obj = j & 3;                    // consumed by serial block j+2
            ull pk = scan_part(nodes_s, samps[32 * (j + 2) + warp],
                               32 * j, (int)crank, CSIZE, lane);
            pk = bfly_min(pk);
            if (lane == 0) stage[obj][warp] = pk;     // local staging
            if (warp == 29 || warp == 30) {           // sample-31 scan split halves
                int t0 = (warp == 29) ? (int)crank : (int)crank + CSIZE;
                ull pk2 = scan_part(nodes_s, samps[32 * (j + 2) + 31],
                                    32 * j, t0, 2 * CSIZE, lane);
                pk2 = bfly_min(pk2);
                int slot = (warp == 29) ? 31 : 32;
                if (lane == 0) stage[obj][slot] = pk2;
            }
            SCAN_BAR();                               // 31 scan warps: staging visible

            // ---- batched cross-CTA send: warp w (w<8) -> CTA w, lane 0 only ----
            if (warp < CSIZE && lane == 0) {
                // backpressure: previous readers of bests[obj] (all dst serials
                // at their block j-2) must have finished before we overwrite
                if (j >= 4)
                    mbar_wait_cluster(mb_free0 + 8 * obj, ((j - 4) >> 2) & 1);
                uint32_t src  = smem_u32(&stage[obj][0]);
                uint32_t dstr = mapa_u32(smem_u32(&bests[obj][crank][0]),
                                         (uint32_t)warp);
                #pragma unroll
                for (int k = 0; k < 17; k++) {        // 34 slots = 17 x 16B
                    ull a0, a1;
                    asm volatile("ld.shared.v2.u64 {%0, %1}, [%2];"
                                 : "=l"(a0), "=l"(a1) : "r"(src + 16 * k));
                    asm volatile("st.shared::cluster.v2.u64 [%0], {%1, %2};"
                                 :: "r"(dstr + 16 * k), "l"(a0), "l"(a1) : "memory");
                }
                mbar_arrive_cluster_remote(mapa_u32(mb_bests0 + 8 * obj,
                                                    (uint32_t)warp));
            }
        }
    }

    __syncthreads();
    CLUSTER_ARRIVE();
    CLUSTER_WAIT();

    if (crank == 0) {
        const float* ns = reinterpret_cast<const float*>(nodes_s);
        for (int i = tid; i < 2 * NNODES; i += NTHREADS)
            out[i] = ns[i];
    }
}

extern "C" void kernel_launch(void* const* d_in, const int* in_sizes, int n_in,
                              void* d_out, int out_size)
{
    const float* state = (const float*)d_in[0];
    const float* goal  = (const float*)d_in[1];
    const float* u     = (const float*)d_in[2];
    const float* r     = (const float*)d_in[3];
    float* out = (float*)d_out;

    cudaFuncSetAttribute(rrt_kernel,
                         cudaFuncAttributeMaxDynamicSharedMemorySize,
                         (int)SMEM_BYTES);
    rrt_kernel<<<CSIZE, NTHREADS, SMEM_BYTES>>>(state, goal, u, r, out);
}